// round 1
// baseline (speedup 1.0000x reference)
#include <cuda_runtime.h>
#include <cstddef>

#define IN_DIM   256
#define OUT_DIM  256
#define NHEAD    8
#define DKDIM    32
#define MAXN     50000

// Scratch (device globals: allocation inside kernel_launch is forbidden)
__device__ float g_Q   [MAXN * OUT_DIM];
__device__ float g_Krel[MAXN * OUT_DIM];
__device__ float g_V   [MAXN * OUT_DIM];
__device__ float g_num [MAXN * OUT_DIM];
__device__ float g_den [MAXN * NHEAD];

// ---------------------------------------------------------------------------
__global__ void zero_kernel(float4* __restrict__ p, int n4) {
    int i = blockIdx.x * blockDim.x + threadIdx.x;
    if (i < n4) p[i] = make_float4(0.f, 0.f, 0.f, 0.f);
}

// ---------------------------------------------------------------------------
// C[M,256] = A[M,256] @ W[256,256]^T + bias (+ rel per out-col).
// A row i comes from A0 if i < split else A1[i-split]  (handles the
// user/item concat without materializing it).
// 128x128 tile, KT=8, 256 threads, 8x8 accumulators per thread.
__global__ __launch_bounds__(256) void gemm256(
    const float* __restrict__ A0, const float* __restrict__ A1, int split,
    const float* __restrict__ W, const float* __restrict__ bias,
    const float* __restrict__ rel,
    float* __restrict__ C, int M)
{
    __shared__ float As[8][128];
    __shared__ float Bs[8][128];

    const int tid = threadIdx.x;
    const int tx = tid & 15, ty = tid >> 4;
    const int m0 = blockIdx.x * 128;
    const int n0 = blockIdx.y * 128;
    const int lr = tid >> 1;          // 0..127 (row within tile)
    const int lk = (tid & 1) * 4;     // 0 or 4 (k offset)

    const float* Aptr = nullptr;
    {
        int arow = m0 + lr;
        if (arow < M)
            Aptr = (arow < split) ? (A0 + (size_t)arow * IN_DIM)
                                  : (A1 + (size_t)(arow - split) * IN_DIM);
    }
    const float* Bptr = W + (size_t)(n0 + lr) * IN_DIM;

    float acc[8][8];
#pragma unroll
    for (int i = 0; i < 8; i++)
#pragma unroll
        for (int j = 0; j < 8; j++) acc[i][j] = 0.f;

    for (int k0 = 0; k0 < IN_DIM; k0 += 8) {
        float4 a = Aptr ? *(const float4*)(Aptr + k0 + lk)
                        : make_float4(0.f, 0.f, 0.f, 0.f);
        float4 b = *(const float4*)(Bptr + k0 + lk);
        __syncthreads();
        As[lk + 0][lr] = a.x; As[lk + 1][lr] = a.y;
        As[lk + 2][lr] = a.z; As[lk + 3][lr] = a.w;
        Bs[lk + 0][lr] = b.x; Bs[lk + 1][lr] = b.y;
        Bs[lk + 2][lr] = b.z; Bs[lk + 3][lr] = b.w;
        __syncthreads();
#pragma unroll
        for (int kk = 0; kk < 8; kk++) {
            float4 a0 = *(const float4*)&As[kk][ty * 4];
            float4 a1 = *(const float4*)&As[kk][ty * 4 + 64];
            float4 b0 = *(const float4*)&Bs[kk][tx * 4];
            float4 b1 = *(const float4*)&Bs[kk][tx * 4 + 64];
            float ra[8] = {a0.x, a0.y, a0.z, a0.w, a1.x, a1.y, a1.z, a1.w};
            float rb[8] = {b0.x, b0.y, b0.z, b0.w, b1.x, b1.y, b1.z, b1.w};
#pragma unroll
            for (int i = 0; i < 8; i++)
#pragma unroll
                for (int j = 0; j < 8; j++)
                    acc[i][j] = fmaf(ra[i], rb[j], acc[i][j]);
        }
    }

    float addv[8];
#pragma unroll
    for (int j = 0; j < 8; j++) {
        int coln = n0 + ((j < 4) ? tx * 4 + j : 64 + tx * 4 + (j - 4));
        addv[j] = bias[coln] + (rel ? rel[coln] : 0.f);
    }
#pragma unroll
    for (int i = 0; i < 8; i++) {
        int rm = m0 + ((i < 4) ? ty * 4 + i : 64 + ty * 4 + (i - 4));
        if (rm >= M) continue;
        float4 o0 = make_float4(acc[i][0] + addv[0], acc[i][1] + addv[1],
                                acc[i][2] + addv[2], acc[i][3] + addv[3]);
        float4 o1 = make_float4(acc[i][4] + addv[4], acc[i][5] + addv[5],
                                acc[i][6] + addv[6], acc[i][7] + addv[7]);
        *(float4*)(C + (size_t)rm * OUT_DIM + n0 + tx * 4)      = o0;
        *(float4*)(C + (size_t)rm * OUT_DIM + n0 + 64 + tx * 4) = o1;
    }
}

// ---------------------------------------------------------------------------
// Vectorized global reduction (sm_90+): 4 floats per red op.
__device__ __forceinline__ void red_add_v4(float* addr, float4 v) {
    asm volatile("red.global.add.v4.f32 [%0], {%1, %2, %3, %4};"
                 :: "l"(addr), "f"(v.x), "f"(v.y), "f"(v.z), "f"(v.w)
                 : "memory");
}

// One warp per edge. Lane l owns dims [8l, 8l+8) -> head h = l/4.
// s_h = Q[col]·(K[row]+rel) per head / sqrt(32); e = exp(s) (no max needed:
// scores are O(1) here, softmax is shift-invariant).
// Accumulate: den[col,h] += e;  num[col,:] += e * V[row,:].
__global__ __launch_bounds__(256) void edge_kernel(
    const int* __restrict__ row, const int* __restrict__ col, int E)
{
    int w = (blockIdx.x * blockDim.x + threadIdx.x) >> 5;
    if (w >= E) return;
    int lane = threadIdx.x & 31;
    int r = __ldg(row + w);
    int c = __ldg(col + w);

    const float4* q = (const float4*)(g_Q    + (size_t)c * OUT_DIM);
    const float4* k = (const float4*)(g_Krel + (size_t)r * OUT_DIM);
    float4 q0 = q[lane * 2], q1 = q[lane * 2 + 1];
    float4 k0 = k[lane * 2], k1 = k[lane * 2 + 1];
    float p = q0.x * k0.x + q0.y * k0.y + q0.z * k0.z + q0.w * k0.w
            + q1.x * k1.x + q1.y * k1.y + q1.z * k1.z + q1.w * k1.w;
    // reduce over the 4 lanes of this head
    p += __shfl_xor_sync(0xFFFFFFFFu, p, 1);
    p += __shfl_xor_sync(0xFFFFFFFFu, p, 2);

    float e = __expf(p * 0.17677669529663687f);   // 1/sqrt(32)

    if ((lane & 3) == 0)
        atomicAdd(&g_den[c * NHEAD + (lane >> 2)], e);

    const float4* v = (const float4*)(g_V + (size_t)r * OUT_DIM);
    float4 v0 = v[lane * 2], v1 = v[lane * 2 + 1];
    v0.x *= e; v0.y *= e; v0.z *= e; v0.w *= e;
    v1.x *= e; v1.y *= e; v1.z *= e; v1.w *= e;
    float* base = g_num + (size_t)c * OUT_DIM + lane * 8;
    red_add_v4(base,     v0);
    red_add_v4(base + 4, v1);
}

// ---------------------------------------------------------------------------
// num[m, h*32+d] /= den[m, h]; den==0 (empty segment) -> 0 (matches JAX
// segment_sum over empty segment).
__global__ void normalize_kernel(int n4)   // n4 = N * 64 float4s
{
    int i = blockIdx.x * blockDim.x + threadIdx.x;
    if (i >= n4) return;
    int m = i >> 6;
    int h = (i & 63) >> 3;
    float d = g_den[m * NHEAD + h];
    float inv = (d > 0.f) ? 1.0f / d : 0.f;
    float4 v = ((float4*)g_num)[i];
    v.x *= inv; v.y *= inv; v.z *= inv; v.w *= inv;
    ((float4*)g_num)[i] = v;
}

// ---------------------------------------------------------------------------
extern "C" void kernel_launch(void* const* d_in, const int* in_sizes, int n_in,
                              void* d_out, int out_size)
{
    const float* x   = (const float*)d_in[0];
    const int*   row = (const int*)  d_in[1];
    const int*   col = (const int*)  d_in[2];
    const float* rel = (const float*)d_in[3];
    const float* ute = (const float*)d_in[4];
    const float* ite = (const float*)d_in[5];
    const float* Wq  = (const float*)d_in[6];
    const float* bq  = (const float*)d_in[7];
    const float* Wk  = (const float*)d_in[8];
    const float* bk  = (const float*)d_in[9];
    const float* Wv  = (const float*)d_in[10];
    const float* bv  = (const float*)d_in[11];
    const float* Wo  = (const float*)d_in[12];
    const float* bo  = (const float*)d_in[13];

    const int N     = in_sizes[0] / IN_DIM;
    const int E     = in_sizes[1];
    const int split = in_sizes[4] / IN_DIM;

    float *pQ, *pK, *pV, *pNum, *pDen;
    cudaGetSymbolAddress((void**)&pQ,   g_Q);
    cudaGetSymbolAddress((void**)&pK,   g_Krel);
    cudaGetSymbolAddress((void**)&pV,   g_V);
    cudaGetSymbolAddress((void**)&pNum, g_num);
    cudaGetSymbolAddress((void**)&pDen, g_den);

    dim3 ggrid((N + 127) / 128, OUT_DIM / 128);

    // Projections
    gemm256<<<ggrid, 256>>>(ute, ite, split, Wq, bq, nullptr, pQ, N);
    gemm256<<<ggrid, 256>>>(ute, ite, split, Wk, bk, rel,     pK, N);
    gemm256<<<ggrid, 256>>>(x,   x,   N,     Wv, bv, nullptr, pV, N);

    // Zero accumulators
    int n4 = N * OUT_DIM / 4;
    zero_kernel<<<(n4 + 255) / 256, 256>>>((float4*)pNum, n4);
    int d4 = (N * NHEAD + 3) / 4;
    zero_kernel<<<(d4 + 255) / 256, 256>>>((float4*)pDen, d4);

    // Edge pass: scores + exp + fused scatter of numerator/denominator
    long long tthreads = (long long)E * 32;
    edge_kernel<<<(int)((tthreads + 255) / 256), 256>>>(row, col, E);

    // Deferred softmax normalization
    normalize_kernel<<<(N * 64 + 255) / 256, 256>>>(N * 64);

    // Output projection
    gemm256<<<ggrid, 256>>>(pNum, pNum, N, Wo, bo, nullptr, (float*)d_out, N);
}

// round 4
// speedup vs baseline: 1.4146x; 1.4146x over previous
#include <cuda_runtime.h>
#include <cuda_bf16.h>
#include <cstdint>
#include <cstddef>

#define IN_DIM   256
#define OUT_DIM  256
#define NHEAD    8
#define MAXN     50000

// ---------------- scratch (device globals; no allocation allowed) ----------
__device__ float g_Q   [MAXN * OUT_DIM];
__device__ float g_Krel[MAXN * OUT_DIM];
__device__ float g_V   [MAXN * OUT_DIM];
__device__ float g_num [MAXN * OUT_DIM];
__device__ float g_den [MAXN * NHEAD];

__device__ __nv_bfloat16 g_TEhi[MAXN * IN_DIM];
__device__ __nv_bfloat16 g_TElo[MAXN * IN_DIM];
__device__ __nv_bfloat16 g_Xhi [MAXN * IN_DIM];
__device__ __nv_bfloat16 g_Xlo [MAXN * IN_DIM];
__device__ __nv_bfloat16 g_Nhi [MAXN * OUT_DIM];
__device__ __nv_bfloat16 g_Nlo [MAXN * OUT_DIM];
__device__ __nv_bfloat16 g_Whi [4 * 256 * 256];
__device__ __nv_bfloat16 g_Wlo [4 * 256 * 256];

// ---------------------------------------------------------------------------
__global__ void zero_kernel(float4* __restrict__ p, int n4) {
    int i = blockIdx.x * blockDim.x + threadIdx.x;
    if (i < n4) p[i] = make_float4(0.f, 0.f, 0.f, 0.f);
}

// ---------------------------------------------------------------------------
// fp32 -> (bf16 hi, bf16 lo) split, with optional concat of two sources.
struct alignas(8) bf4 { __nv_bfloat16 a, b, c, d; };

__global__ void cvt_kernel(const float4* __restrict__ s0,
                           const float4* __restrict__ s1, int split4,
                           __nv_bfloat16* __restrict__ hi,
                           __nv_bfloat16* __restrict__ lo, int n4)
{
    int i = blockIdx.x * blockDim.x + threadIdx.x;
    if (i >= n4) return;
    float4 v = (i < split4) ? s0[i] : s1[i - split4];
    bf4 h, l;
    h.a = __float2bfloat16_rn(v.x); l.a = __float2bfloat16_rn(v.x - __bfloat162float(h.a));
    h.b = __float2bfloat16_rn(v.y); l.b = __float2bfloat16_rn(v.y - __bfloat162float(h.b));
    h.c = __float2bfloat16_rn(v.z); l.c = __float2bfloat16_rn(v.z - __bfloat162float(h.c));
    h.d = __float2bfloat16_rn(v.w); l.d = __float2bfloat16_rn(v.w - __bfloat162float(h.d));
    ((bf4*)hi)[i] = h;
    ((bf4*)lo)[i] = l;
}

// ---------------------------------------------------------------------------
// mma helpers (plain functions, no lambdas)
__device__ __forceinline__ void ldsm4(uint32_t* r, uint32_t addr) {
    asm volatile("ldmatrix.sync.aligned.m8n8.x4.shared.b16 {%0,%1,%2,%3}, [%4];"
                 : "=r"(r[0]), "=r"(r[1]), "=r"(r[2]), "=r"(r[3]) : "r"(addr));
}
__device__ __forceinline__ void mma16816(float* d, const uint32_t* a,
                                         uint32_t b0, uint32_t b1) {
    asm volatile("mma.sync.aligned.m16n8k16.row.col.f32.bf16.bf16.f32 "
                 "{%0,%1,%2,%3}, {%4,%5,%6,%7}, {%8,%9}, {%0,%1,%2,%3};"
                 : "+f"(d[0]), "+f"(d[1]), "+f"(d[2]), "+f"(d[3])
                 : "r"(a[0]), "r"(a[1]), "r"(a[2]), "r"(a[3]), "r"(b0), "r"(b1));
}
__device__ __forceinline__ void cp16(uint32_t dst, const void* src, bool valid) {
    int sz = valid ? 16 : 0;
    asm volatile("cp.async.cg.shared.global [%0], [%1], 16, %2;"
                 :: "r"(dst), "l"(src), "r"(sz));
}

#define PITCH 40                       // bf16 elems per smem row (conflict-free)
#define PLANE (128 * PITCH * 2)        // 10240 B per operand plane
#define STAGE (4 * PLANE)              // 40960 B  (Ahi, Alo, Bhi, Blo)

__device__ __forceinline__ void gemm_prefetch(
    uint32_t d,
    const __nv_bfloat16* pah, const __nv_bfloat16* pal,
    const __nv_bfloat16* pbh, const __nv_bfloat16* pbl, bool a_valid)
{
    cp16(d + 0u * PLANE,       pah,     a_valid);
    cp16(d + 0u * PLANE + 16u, pah + 8, a_valid);
    cp16(d + 1u * PLANE,       pal,     a_valid);
    cp16(d + 1u * PLANE + 16u, pal + 8, a_valid);
    cp16(d + 2u * PLANE,       pbh,     true);
    cp16(d + 2u * PLANE + 16u, pbh + 8, true);
    cp16(d + 3u * PLANE,       pbl,     true);
    cp16(d + 3u * PLANE + 16u, pbl + 8, true);
    asm volatile("cp.async.commit_group;");
}

__device__ __forceinline__ void gemm_compute(
    uint32_t sb, uint32_t aoff, uint32_t boff, float acc[2][8][4])
{
#pragma unroll
    for (int kb = 0; kb < 2; kb++) {
        uint32_t ah[2][4], al[2][4];
#pragma unroll
        for (int ms = 0; ms < 2; ms++) {
            ldsm4(ah[ms], sb + 0u * PLANE + aoff + (uint32_t)(ms * 16 * PITCH * 2 + kb * 32));
            ldsm4(al[ms], sb + 1u * PLANE + aoff + (uint32_t)(ms * 16 * PITCH * 2 + kb * 32));
        }
#pragma unroll
        for (int np = 0; np < 4; np++) {
            uint32_t bh[4], bl[4];
            ldsm4(bh, sb + 2u * PLANE + boff + (uint32_t)(np * 16 * PITCH * 2 + kb * 32));
            ldsm4(bl, sb + 3u * PLANE + boff + (uint32_t)(np * 16 * PITCH * 2 + kb * 32));
#pragma unroll
            for (int ms = 0; ms < 2; ms++) {
                mma16816(acc[ms][np * 2 + 0], ah[ms], bh[0], bh[1]); // hi*hi
                mma16816(acc[ms][np * 2 + 1], ah[ms], bh[2], bh[3]);
                mma16816(acc[ms][np * 2 + 0], ah[ms], bl[0], bl[1]); // hi*lo
                mma16816(acc[ms][np * 2 + 1], ah[ms], bl[2], bl[3]);
                mma16816(acc[ms][np * 2 + 0], al[ms], bh[0], bh[1]); // lo*hi
                mma16816(acc[ms][np * 2 + 1], al[ms], bh[2], bh[3]);
            }
        }
    }
}

// C[M,256] = A[M,256] @ W[256,256]^T + bias (+rel), bf16x3 via mma.sync.
// Block tile 128x128, 8 warps (4x2), K-chunks of 32, cp.async double buffer.
__global__ __launch_bounds__(256) void gemm_bf16x3(
    const __nv_bfloat16* __restrict__ Ahi, const __nv_bfloat16* __restrict__ Alo,
    const __nv_bfloat16* __restrict__ Whi, const __nv_bfloat16* __restrict__ Wlo,
    const float* __restrict__ bias, const float* __restrict__ rel,
    float* __restrict__ C, int M)
{
    extern __shared__ char smem[];
    uint32_t sbase = (uint32_t)__cvta_generic_to_shared(smem);

    const int tid = threadIdx.x, lane = tid & 31, wid = tid >> 5;
    const int warp_m = wid & 3, warp_n = wid >> 2;
    const int m0 = blockIdx.x * 128, n0 = blockIdx.y * 128;

    // global->smem load mapping: 2 threads per tile row, 2x16B per plane
    const int lrow = tid >> 1;
    const int lcs  = (tid & 1) * 16;
    const bool a_valid = (m0 + lrow) < M;
    const size_t a_row = (size_t)((m0 + lrow) < M ? (m0 + lrow) : (M - 1)) * 256;
    const size_t b_row = (size_t)(n0 + lrow) * 256;
    const uint32_t doff = (uint32_t)(lrow * PITCH + lcs) * 2u;

    float acc[2][8][4];
#pragma unroll
    for (int i = 0; i < 2; i++)
#pragma unroll
        for (int j = 0; j < 8; j++)
#pragma unroll
            for (int k = 0; k < 4; k++) acc[i][j][k] = 0.f;

    // ldmatrix per-lane offsets (bytes)
    const uint32_t aoff = (uint32_t)(((warp_m * 32 + (lane & 15)) * PITCH
                                      + (lane >> 4) * 8) * 2);
    const uint32_t boff = (uint32_t)(((warp_n * 64 + (lane >> 4) * 8 + (lane & 7)) * PITCH
                                      + ((lane >> 3) & 1) * 8) * 2);

    gemm_prefetch(sbase + 0u * STAGE + doff,
                  Ahi + a_row + 0 + lcs, Alo + a_row + 0 + lcs,
                  Whi + b_row + 0 + lcs, Wlo + b_row + 0 + lcs, a_valid);
    gemm_prefetch(sbase + 1u * STAGE + doff,
                  Ahi + a_row + 32 + lcs, Alo + a_row + 32 + lcs,
                  Whi + b_row + 32 + lcs, Wlo + b_row + 32 + lcs, a_valid);

#pragma unroll
    for (int c = 0; c < 8; c++) {
        if (c < 7) asm volatile("cp.async.wait_group 1;");
        else       asm volatile("cp.async.wait_group 0;");
        __syncthreads();
        gemm_compute(sbase + (uint32_t)(c & 1) * STAGE, aoff, boff, acc);
        __syncthreads();
        if (c + 2 < 8) {
            int k0 = (c + 2) * 32;
            gemm_prefetch(sbase + (uint32_t)(c & 1) * STAGE + doff,
                          Ahi + a_row + k0 + lcs, Alo + a_row + k0 + lcs,
                          Whi + b_row + k0 + lcs, Wlo + b_row + k0 + lcs, a_valid);
        }
    }

    // epilogue
    const int crow  = warp_m * 32 + (lane >> 2);
    const int ccol0 = warp_n * 64 + (lane & 3) * 2;
#pragma unroll
    for (int ns = 0; ns < 8; ns++) {
        int col = n0 + ccol0 + ns * 8;
        float av0 = bias[col]     + (rel ? rel[col]     : 0.f);
        float av1 = bias[col + 1] + (rel ? rel[col + 1] : 0.f);
#pragma unroll
        for (int ms = 0; ms < 2; ms++) {
            int r = m0 + crow + ms * 16;
            if (r < M) {
                float2 o = make_float2(acc[ms][ns][0] + av0, acc[ms][ns][1] + av1);
                *(float2*)(C + (size_t)r * 256 + col) = o;
            }
            if (r + 8 < M) {
                float2 o = make_float2(acc[ms][ns][2] + av0, acc[ms][ns][3] + av1);
                *(float2*)(C + (size_t)(r + 8) * 256 + col) = o;
            }
        }
    }
}

// ---------------------------------------------------------------------------
__device__ __forceinline__ void red_add_v4(float* addr, float4 v) {
    asm volatile("red.global.add.v4.f32 [%0], {%1, %2, %3, %4};"
                 :: "l"(addr), "f"(v.x), "f"(v.y), "f"(v.z), "f"(v.w)
                 : "memory");
}

// One warp per edge.
__global__ __launch_bounds__(256) void edge_kernel(
    const int* __restrict__ row, const int* __restrict__ col, int E)
{
    int w = (blockIdx.x * blockDim.x + threadIdx.x) >> 5;
    if (w >= E) return;
    int lane = threadIdx.x & 31;
    int r = __ldg(row + w);
    int c = __ldg(col + w);

    const float4* q = (const float4*)(g_Q    + (size_t)c * OUT_DIM);
    const float4* k = (const float4*)(g_Krel + (size_t)r * OUT_DIM);
    float4 q0 = q[lane * 2], q1 = q[lane * 2 + 1];
    float4 k0 = k[lane * 2], k1 = k[lane * 2 + 1];
    float p = q0.x * k0.x + q0.y * k0.y + q0.z * k0.z + q0.w * k0.w
            + q1.x * k1.x + q1.y * k1.y + q1.z * k1.z + q1.w * k1.w;
    p += __shfl_xor_sync(0xFFFFFFFFu, p, 1);
    p += __shfl_xor_sync(0xFFFFFFFFu, p, 2);

    float e = __expf(p * 0.17677669529663687f);   // 1/sqrt(32)

    if ((lane & 3) == 0)
        atomicAdd(&g_den[c * NHEAD + (lane >> 2)], e);

    const float4* v = (const float4*)(g_V + (size_t)r * OUT_DIM);
    float4 v0 = v[lane * 2], v1 = v[lane * 2 + 1];
    v0.x *= e; v0.y *= e; v0.z *= e; v0.w *= e;
    v1.x *= e; v1.y *= e; v1.z *= e; v1.w *= e;
    float* base = g_num + (size_t)c * OUT_DIM + lane * 8;
    red_add_v4(base,     v0);
    red_add_v4(base + 4, v1);
}

// ---------------------------------------------------------------------------
__global__ void normalize_kernel(int n4)   // n4 = N * 64 float4s
{
    int i = blockIdx.x * blockDim.x + threadIdx.x;
    if (i >= n4) return;
    int m = i >> 6;
    int h = (i & 63) >> 3;
    float d = g_den[m * NHEAD + h];
    float inv = (d > 0.f) ? 1.0f / d : 0.f;
    float4 v = ((float4*)g_num)[i];
    v.x *= inv; v.y *= inv; v.z *= inv; v.w *= inv;
    ((float4*)g_num)[i] = v;
}

// ---------------------------------------------------------------------------
extern "C" void kernel_launch(void* const* d_in, const int* in_sizes, int n_in,
                              void* d_out, int out_size)
{
    const float* x   = (const float*)d_in[0];
    const int*   row = (const int*)  d_in[1];
    const int*   col = (const int*)  d_in[2];
    const float* rel = (const float*)d_in[3];
    const float* ute = (const float*)d_in[4];
    const float* ite = (const float*)d_in[5];
    const float* Wq  = (const float*)d_in[6];
    const float* bq  = (const float*)d_in[7];
    const float* Wk  = (const float*)d_in[8];
    const float* bk  = (const float*)d_in[9];
    const float* Wv  = (const float*)d_in[10];
    const float* bv  = (const float*)d_in[11];
    const float* Wo  = (const float*)d_in[12];
    const float* bo  = (const float*)d_in[13];

    const int N     = in_sizes[0] / IN_DIM;
    const int E     = in_sizes[1];
    const int split = in_sizes[4] / IN_DIM;

    float *pQ, *pK, *pV, *pNum, *pDen;
    __nv_bfloat16 *pTEh, *pTEl, *pXh, *pXl, *pNh, *pNl, *pWh, *pWl;
    cudaGetSymbolAddress((void**)&pQ,   g_Q);
    cudaGetSymbolAddress((void**)&pK,   g_Krel);
    cudaGetSymbolAddress((void**)&pV,   g_V);
    cudaGetSymbolAddress((void**)&pNum, g_num);
    cudaGetSymbolAddress((void**)&pDen, g_den);
    cudaGetSymbolAddress((void**)&pTEh, g_TEhi);
    cudaGetSymbolAddress((void**)&pTEl, g_TElo);
    cudaGetSymbolAddress((void**)&pXh,  g_Xhi);
    cudaGetSymbolAddress((void**)&pXl,  g_Xlo);
    cudaGetSymbolAddress((void**)&pNh,  g_Nhi);
    cudaGetSymbolAddress((void**)&pNl,  g_Nlo);
    cudaGetSymbolAddress((void**)&pWh,  g_Whi);
    cudaGetSymbolAddress((void**)&pWl,  g_Wlo);

    cudaFuncSetAttribute(gemm_bf16x3,
                         cudaFuncAttributeMaxDynamicSharedMemorySize, 2 * STAGE);

    const int n4 = N * IN_DIM / 4;          // float4 count for [N,256]
    const int w4 = 256 * 256 / 4;

    // fp32 -> bf16 hi/lo conversions
    cvt_kernel<<<(n4 + 255) / 256, 256>>>((const float4*)ute, (const float4*)ite,
                                          split * (IN_DIM / 4), pTEh, pTEl, n4);
    cvt_kernel<<<(n4 + 255) / 256, 256>>>((const float4*)x, (const float4*)x,
                                          n4, pXh, pXl, n4);
    const float* Ws[4] = {Wq, Wk, Wv, Wo};
    for (int i = 0; i < 4; i++)
        cvt_kernel<<<(w4 + 255) / 256, 256>>>((const float4*)Ws[i], (const float4*)Ws[i],
                                              w4, pWh + i * 65536, pWl + i * 65536, w4);

    dim3 ggrid((N + 127) / 128, 2);

    // Projections (tensor cores)
    gemm_bf16x3<<<ggrid, 256, 2 * STAGE>>>(pTEh, pTEl, pWh + 0 * 65536, pWl + 0 * 65536,
                                           bq, nullptr, pQ, N);
    gemm_bf16x3<<<ggrid, 256, 2 * STAGE>>>(pTEh, pTEl, pWh + 1 * 65536, pWl + 1 * 65536,
                                           bk, rel, pK, N);
    gemm_bf16x3<<<ggrid, 256, 2 * STAGE>>>(pXh, pXl, pWh + 2 * 65536, pWl + 2 * 65536,
                                           bv, nullptr, pV, N);

    // Zero accumulators
    int a4 = N * OUT_DIM / 4;
    zero_kernel<<<(a4 + 255) / 256, 256>>>((float4*)pNum, a4);
    int d4 = (N * NHEAD + 3) / 4;
    zero_kernel<<<(d4 + 255) / 256, 256>>>((float4*)pDen, d4);

    // Edge pass
    long long tthreads = (long long)E * 32;
    edge_kernel<<<(int)((tthreads + 255) / 256), 256>>>(row, col, E);

    // Deferred softmax normalization
    normalize_kernel<<<(N * 64 + 255) / 256, 256>>>(N * 64);

    // Output projection
    cvt_kernel<<<(a4 + 255) / 256, 256>>>((const float4*)pNum, (const float4*)pNum,
                                          a4, pNh, pNl, a4);
    gemm_bf16x3<<<ggrid, 256, 2 * STAGE>>>(pNh, pNl, pWh + 3 * 65536, pWl + 3 * 65536,
                                           bo, nullptr, (float*)d_out, N);
}

// round 5
// speedup vs baseline: 1.8998x; 1.3430x over previous
#include <cuda_runtime.h>
#include <cuda_bf16.h>
#include <cstdint>
#include <cstddef>

#define IN_DIM   256
#define OUT_DIM  256
#define NHEAD    8
#define MAXN     50000
#define MAXE     800000

// ---------------- scratch (device globals; no allocation allowed) ----------
__device__ float g_Q   [MAXN * OUT_DIM];
__device__ float g_Krel[MAXN * OUT_DIM];
__device__ float g_V   [MAXN * OUT_DIM];

__device__ int   g_counts [MAXN + 4];
__device__ int   g_offsets[MAXN + 4];
__device__ int   g_csr    [MAXE];

__device__ __nv_bfloat16 g_TEhi[MAXN * IN_DIM];
__device__ __nv_bfloat16 g_TElo[MAXN * IN_DIM];
__device__ __nv_bfloat16 g_Xhi [MAXN * IN_DIM];
__device__ __nv_bfloat16 g_Xlo [MAXN * IN_DIM];
__device__ __nv_bfloat16 g_Nhi [MAXN * OUT_DIM];
__device__ __nv_bfloat16 g_Nlo [MAXN * OUT_DIM];
__device__ __nv_bfloat16 g_Whi [4 * 256 * 256];
__device__ __nv_bfloat16 g_Wlo [4 * 256 * 256];

// ---------------------------------------------------------------------------
__global__ void zero_kernel(float4* __restrict__ p, int n4) {
    int i = blockIdx.x * blockDim.x + threadIdx.x;
    if (i < n4) p[i] = make_float4(0.f, 0.f, 0.f, 0.f);
}

// ---------------------------------------------------------------------------
// fp32 -> (bf16 hi, bf16 lo) split, with optional concat of two sources.
struct alignas(8) bf4 { __nv_bfloat16 a, b, c, d; };

__global__ void cvt_kernel(const float4* __restrict__ s0,
                           const float4* __restrict__ s1, int split4,
                           __nv_bfloat16* __restrict__ hi,
                           __nv_bfloat16* __restrict__ lo, int n4)
{
    int i = blockIdx.x * blockDim.x + threadIdx.x;
    if (i >= n4) return;
    float4 v = (i < split4) ? s0[i] : s1[i - split4];
    bf4 h, l;
    h.a = __float2bfloat16_rn(v.x); l.a = __float2bfloat16_rn(v.x - __bfloat162float(h.a));
    h.b = __float2bfloat16_rn(v.y); l.b = __float2bfloat16_rn(v.y - __bfloat162float(h.b));
    h.c = __float2bfloat16_rn(v.z); l.c = __float2bfloat16_rn(v.z - __bfloat162float(h.c));
    h.d = __float2bfloat16_rn(v.w); l.d = __float2bfloat16_rn(v.w - __bfloat162float(h.d));
    ((bf4*)hi)[i] = h;
    ((bf4*)lo)[i] = l;
}

// ---------------------------------------------------------------------------
// mma helpers
__device__ __forceinline__ void ldsm4(uint32_t* r, uint32_t addr) {
    asm volatile("ldmatrix.sync.aligned.m8n8.x4.shared.b16 {%0,%1,%2,%3}, [%4];"
                 : "=r"(r[0]), "=r"(r[1]), "=r"(r[2]), "=r"(r[3]) : "r"(addr));
}
__device__ __forceinline__ void mma16816(float* d, const uint32_t* a,
                                         uint32_t b0, uint32_t b1) {
    asm volatile("mma.sync.aligned.m16n8k16.row.col.f32.bf16.bf16.f32 "
                 "{%0,%1,%2,%3}, {%4,%5,%6,%7}, {%8,%9}, {%0,%1,%2,%3};"
                 : "+f"(d[0]), "+f"(d[1]), "+f"(d[2]), "+f"(d[3])
                 : "r"(a[0]), "r"(a[1]), "r"(a[2]), "r"(a[3]), "r"(b0), "r"(b1));
}
__device__ __forceinline__ void cp16(uint32_t dst, const void* src, bool valid) {
    int sz = valid ? 16 : 0;
    asm volatile("cp.async.cg.shared.global [%0], [%1], 16, %2;"
                 :: "r"(dst), "l"(src), "r"(sz));
}

#define PITCH 40                       // bf16 elems per smem row (conflict-free)
#define PLANE (128 * PITCH * 2)        // 10240 B per operand plane
#define STAGE (4 * PLANE)              // 40960 B  (Ahi, Alo, Bhi, Blo)

__device__ __forceinline__ void gemm_prefetch(
    uint32_t d,
    const __nv_bfloat16* pah, const __nv_bfloat16* pal,
    const __nv_bfloat16* pbh, const __nv_bfloat16* pbl, bool a_valid)
{
    cp16(d + 0u * PLANE,       pah,     a_valid);
    cp16(d + 0u * PLANE + 16u, pah + 8, a_valid);
    cp16(d + 1u * PLANE,       pal,     a_valid);
    cp16(d + 1u * PLANE + 16u, pal + 8, a_valid);
    cp16(d + 2u * PLANE,       pbh,     true);
    cp16(d + 2u * PLANE + 16u, pbh + 8, true);
    cp16(d + 3u * PLANE,       pbl,     true);
    cp16(d + 3u * PLANE + 16u, pbl + 8, true);
    asm volatile("cp.async.commit_group;");
}

__device__ __forceinline__ void gemm_compute(
    uint32_t sb, uint32_t aoff, uint32_t boff, float acc[2][8][4])
{
#pragma unroll
    for (int kb = 0; kb < 2; kb++) {
        uint32_t ah[2][4], al[2][4];
#pragma unroll
        for (int ms = 0; ms < 2; ms++) {
            ldsm4(ah[ms], sb + 0u * PLANE + aoff + (uint32_t)(ms * 16 * PITCH * 2 + kb * 32));
            ldsm4(al[ms], sb + 1u * PLANE + aoff + (uint32_t)(ms * 16 * PITCH * 2 + kb * 32));
        }
#pragma unroll
        for (int np = 0; np < 4; np++) {
            uint32_t bh[4], bl[4];
            ldsm4(bh, sb + 2u * PLANE + boff + (uint32_t)(np * 16 * PITCH * 2 + kb * 32));
            ldsm4(bl, sb + 3u * PLANE + boff + (uint32_t)(np * 16 * PITCH * 2 + kb * 32));
#pragma unroll
            for (int ms = 0; ms < 2; ms++) {
                mma16816(acc[ms][np * 2 + 0], ah[ms], bh[0], bh[1]); // hi*hi
                mma16816(acc[ms][np * 2 + 1], ah[ms], bh[2], bh[3]);
                mma16816(acc[ms][np * 2 + 0], ah[ms], bl[0], bl[1]); // hi*lo
                mma16816(acc[ms][np * 2 + 1], ah[ms], bl[2], bl[3]);
                mma16816(acc[ms][np * 2 + 0], al[ms], bh[0], bh[1]); // lo*hi
                mma16816(acc[ms][np * 2 + 1], al[ms], bh[2], bh[3]);
            }
        }
    }
}

// C[M,256] = A[M,256] @ W[256,256]^T + bias (+rel), bf16x3 via mma.sync.
__global__ __launch_bounds__(256) void gemm_bf16x3(
    const __nv_bfloat16* __restrict__ Ahi, const __nv_bfloat16* __restrict__ Alo,
    const __nv_bfloat16* __restrict__ Whi, const __nv_bfloat16* __restrict__ Wlo,
    const float* __restrict__ bias, const float* __restrict__ rel,
    float* __restrict__ C, int M)
{
    extern __shared__ char smem[];
    uint32_t sbase = (uint32_t)__cvta_generic_to_shared(smem);

    const int tid = threadIdx.x, lane = tid & 31, wid = tid >> 5;
    const int warp_m = wid & 3, warp_n = wid >> 2;
    const int m0 = blockIdx.x * 128, n0 = blockIdx.y * 128;

    const int lrow = tid >> 1;
    const int lcs  = (tid & 1) * 16;
    const bool a_valid = (m0 + lrow) < M;
    const size_t a_row = (size_t)((m0 + lrow) < M ? (m0 + lrow) : (M - 1)) * 256;
    const size_t b_row = (size_t)(n0 + lrow) * 256;
    const uint32_t doff = (uint32_t)(lrow * PITCH + lcs) * 2u;

    float acc[2][8][4];
#pragma unroll
    for (int i = 0; i < 2; i++)
#pragma unroll
        for (int j = 0; j < 8; j++)
#pragma unroll
            for (int k = 0; k < 4; k++) acc[i][j][k] = 0.f;

    const uint32_t aoff = (uint32_t)(((warp_m * 32 + (lane & 15)) * PITCH
                                      + (lane >> 4) * 8) * 2);
    const uint32_t boff = (uint32_t)(((warp_n * 64 + (lane >> 4) * 8 + (lane & 7)) * PITCH
                                      + ((lane >> 3) & 1) * 8) * 2);

    gemm_prefetch(sbase + 0u * STAGE + doff,
                  Ahi + a_row + 0 + lcs, Alo + a_row + 0 + lcs,
                  Whi + b_row + 0 + lcs, Wlo + b_row + 0 + lcs, a_valid);
    gemm_prefetch(sbase + 1u * STAGE + doff,
                  Ahi + a_row + 32 + lcs, Alo + a_row + 32 + lcs,
                  Whi + b_row + 32 + lcs, Wlo + b_row + 32 + lcs, a_valid);

#pragma unroll
    for (int c = 0; c < 8; c++) {
        if (c < 7) asm volatile("cp.async.wait_group 1;");
        else       asm volatile("cp.async.wait_group 0;");
        __syncthreads();
        gemm_compute(sbase + (uint32_t)(c & 1) * STAGE, aoff, boff, acc);
        __syncthreads();
        if (c + 2 < 8) {
            int k0 = (c + 2) * 32;
            gemm_prefetch(sbase + (uint32_t)(c & 1) * STAGE + doff,
                          Ahi + a_row + k0 + lcs, Alo + a_row + k0 + lcs,
                          Whi + b_row + k0 + lcs, Wlo + b_row + k0 + lcs, a_valid);
        }
    }

    const int crow  = warp_m * 32 + (lane >> 2);
    const int ccol0 = warp_n * 64 + (lane & 3) * 2;
#pragma unroll
    for (int ns = 0; ns < 8; ns++) {
        int col = n0 + ccol0 + ns * 8;
        float av0 = bias[col]     + (rel ? rel[col]     : 0.f);
        float av1 = bias[col + 1] + (rel ? rel[col + 1] : 0.f);
#pragma unroll
        for (int ms = 0; ms < 2; ms++) {
            int r = m0 + crow + ms * 16;
            if (r < M) {
                float2 o = make_float2(acc[ms][ns][0] + av0, acc[ms][ns][1] + av1);
                *(float2*)(C + (size_t)r * 256 + col) = o;
            }
            if (r + 8 < M) {
                float2 o = make_float2(acc[ms][ns][2] + av0, acc[ms][ns][3] + av1);
                *(float2*)(C + (size_t)(r + 8) * 256 + col) = o;
            }
        }
    }
}

// ---------------------------------------------------------------------------
// CSR build: histogram -> scan -> fill
__global__ void hist_kernel(const int* __restrict__ col, int E) {
    int i = blockIdx.x * blockDim.x + threadIdx.x;
    if (i < E) atomicAdd(&g_counts[col[i]], 1);
}

// Single-block inclusive scan (chunked), offsets[0]=0, offsets[i+1]=sum<=i.
__global__ void scan_kernel(int n) {
    __shared__ int sdata[1024];
    __shared__ int carry;
    int tid = threadIdx.x;
    if (tid == 0) { carry = 0; g_offsets[0] = 0; }
    __syncthreads();
    for (int base = 0; base < n; base += 1024) {
        int i = base + tid;
        int v = (i < n) ? g_counts[i] : 0;
        sdata[tid] = v;
        __syncthreads();
#pragma unroll
        for (int off = 1; off < 1024; off <<= 1) {
            int t = (tid >= off) ? sdata[tid - off] : 0;
            __syncthreads();
            sdata[tid] += t;
            __syncthreads();
        }
        if (i < n) g_offsets[i + 1] = carry + sdata[tid];
        int total = sdata[1023];
        __syncthreads();
        if (tid == 0) carry += total;
        __syncthreads();
    }
}

// After fill, g_offsets[c] = original offsets[c+1] (end of segment c).
// So segment c = [ (c>0 ? g_offsets[c-1] : 0), g_offsets[c] ).
__global__ void fill_kernel(const int* __restrict__ row,
                            const int* __restrict__ col, int E) {
    int i = blockIdx.x * blockDim.x + threadIdx.x;
    if (i < E) {
        int pos = atomicAdd(&g_offsets[col[i]], 1);
        g_csr[pos] = row[i];
    }
}

// ---------------------------------------------------------------------------
// One warp per destination column c. Q[c] register-resident; iterate edges,
// accumulate softmax numerator/denominator in registers; normalize; emit
// bf16 hi/lo planes directly for the Wo GEMM.
__global__ __launch_bounds__(256) void attn_kernel(int N)
{
    int c = (blockIdx.x * blockDim.x + threadIdx.x) >> 5;
    if (c >= N) return;
    int lane = threadIdx.x & 31;

    int start = (c > 0) ? __ldg(&g_offsets[c - 1]) : 0;
    int end   = __ldg(&g_offsets[c]);

    const float4* qp = (const float4*)(g_Q + (size_t)c * OUT_DIM);
    float4 q0 = qp[lane * 2], q1 = qp[lane * 2 + 1];

    float4 n0 = make_float4(0.f, 0.f, 0.f, 0.f);
    float4 n1 = make_float4(0.f, 0.f, 0.f, 0.f);
    float den = 0.f;

    for (int i = start; i < end; i++) {
        int r = __ldg(&g_csr[i]);
        const float4* kp = (const float4*)(g_Krel + (size_t)r * OUT_DIM);
        float4 k0 = kp[lane * 2], k1 = kp[lane * 2 + 1];
        float p = q0.x * k0.x + q0.y * k0.y + q0.z * k0.z + q0.w * k0.w
                + q1.x * k1.x + q1.y * k1.y + q1.z * k1.z + q1.w * k1.w;
        p += __shfl_xor_sync(0xFFFFFFFFu, p, 1);   // reduce over the head's
        p += __shfl_xor_sync(0xFFFFFFFFu, p, 2);   // 4-lane quad
        float e = __expf(p * 0.17677669529663687f);  // 1/sqrt(32)

        const float4* vp = (const float4*)(g_V + (size_t)r * OUT_DIM);
        float4 v0 = vp[lane * 2], v1 = vp[lane * 2 + 1];
        n0.x += e * v0.x; n0.y += e * v0.y; n0.z += e * v0.z; n0.w += e * v0.w;
        n1.x += e * v1.x; n1.y += e * v1.y; n1.z += e * v1.z; n1.w += e * v1.w;
        den += e;   // all 4 lanes of a head hold identical e -> identical den
    }

    float inv = (den > 0.f) ? 1.0f / den : 0.f;
    n0.x *= inv; n0.y *= inv; n0.z *= inv; n0.w *= inv;
    n1.x *= inv; n1.y *= inv; n1.z *= inv; n1.w *= inv;

    bf4 h0, l0, h1, l1;
    h0.a = __float2bfloat16_rn(n0.x); l0.a = __float2bfloat16_rn(n0.x - __bfloat162float(h0.a));
    h0.b = __float2bfloat16_rn(n0.y); l0.b = __float2bfloat16_rn(n0.y - __bfloat162float(h0.b));
    h0.c = __float2bfloat16_rn(n0.z); l0.c = __float2bfloat16_rn(n0.z - __bfloat162float(h0.c));
    h0.d = __float2bfloat16_rn(n0.w); l0.d = __float2bfloat16_rn(n0.w - __bfloat162float(h0.d));
    h1.a = __float2bfloat16_rn(n1.x); l1.a = __float2bfloat16_rn(n1.x - __bfloat162float(h1.a));
    h1.b = __float2bfloat16_rn(n1.y); l1.b = __float2bfloat16_rn(n1.y - __bfloat162float(h1.b));
    h1.c = __float2bfloat16_rn(n1.z); l1.c = __float2bfloat16_rn(n1.z - __bfloat162float(h1.c));
    h1.d = __float2bfloat16_rn(n1.w); l1.d = __float2bfloat16_rn(n1.w - __bfloat162float(h1.d));

    bf4* hp = (bf4*)(g_Nhi + (size_t)c * OUT_DIM);
    bf4* lp = (bf4*)(g_Nlo + (size_t)c * OUT_DIM);
    hp[lane * 2]     = h0;  hp[lane * 2 + 1] = h1;
    lp[lane * 2]     = l0;  lp[lane * 2 + 1] = l1;
}

// ---------------------------------------------------------------------------
extern "C" void kernel_launch(void* const* d_in, const int* in_sizes, int n_in,
                              void* d_out, int out_size)
{
    const float* x   = (const float*)d_in[0];
    const int*   row = (const int*)  d_in[1];
    const int*   col = (const int*)  d_in[2];
    const float* rel = (const float*)d_in[3];
    const float* ute = (const float*)d_in[4];
    const float* ite = (const float*)d_in[5];
    const float* Wq  = (const float*)d_in[6];
    const float* bq  = (const float*)d_in[7];
    const float* Wk  = (const float*)d_in[8];
    const float* bk  = (const float*)d_in[9];
    const float* Wv  = (const float*)d_in[10];
    const float* bv  = (const float*)d_in[11];
    const float* Wo  = (const float*)d_in[12];
    const float* bo  = (const float*)d_in[13];

    const int N     = in_sizes[0] / IN_DIM;
    const int E     = in_sizes[1];
    const int split = in_sizes[4] / IN_DIM;

    float *pQ, *pK, *pV;
    int *pCounts;
    __nv_bfloat16 *pTEh, *pTEl, *pXh, *pXl, *pNh, *pNl, *pWh, *pWl;
    cudaGetSymbolAddress((void**)&pQ,     g_Q);
    cudaGetSymbolAddress((void**)&pK,     g_Krel);
    cudaGetSymbolAddress((void**)&pV,     g_V);
    cudaGetSymbolAddress((void**)&pCounts,g_counts);
    cudaGetSymbolAddress((void**)&pTEh,   g_TEhi);
    cudaGetSymbolAddress((void**)&pTEl,   g_TElo);
    cudaGetSymbolAddress((void**)&pXh,    g_Xhi);
    cudaGetSymbolAddress((void**)&pXl,    g_Xlo);
    cudaGetSymbolAddress((void**)&pNh,    g_Nhi);
    cudaGetSymbolAddress((void**)&pNl,    g_Nlo);
    cudaGetSymbolAddress((void**)&pWh,    g_Whi);
    cudaGetSymbolAddress((void**)&pWl,    g_Wlo);

    cudaFuncSetAttribute(gemm_bf16x3,
                         cudaFuncAttributeMaxDynamicSharedMemorySize, 2 * STAGE);

    const int n4 = N * IN_DIM / 4;
    const int w4 = 256 * 256 / 4;

    // fp32 -> bf16 hi/lo conversions
    cvt_kernel<<<(n4 + 255) / 256, 256>>>((const float4*)ute, (const float4*)ite,
                                          split * (IN_DIM / 4), pTEh, pTEl, n4);
    cvt_kernel<<<(n4 + 255) / 256, 256>>>((const float4*)x, (const float4*)x,
                                          n4, pXh, pXl, n4);
    const float* Ws[4] = {Wq, Wk, Wv, Wo};
    for (int i = 0; i < 4; i++)
        cvt_kernel<<<(w4 + 255) / 256, 256>>>((const float4*)Ws[i], (const float4*)Ws[i],
                                              w4, pWh + i * 65536, pWl + i * 65536, w4);

    // CSR build (independent of GEMMs; same stream serializes fine)
    int c4 = (N + 3) / 4;
    zero_kernel<<<(c4 + 255) / 256, 256>>>((float4*)pCounts, c4);
    hist_kernel<<<(E + 255) / 256, 256>>>(col, E);
    scan_kernel<<<1, 1024>>>(N);
    fill_kernel<<<(E + 255) / 256, 256>>>(row, col, E);

    dim3 ggrid((N + 127) / 128, 2);

    // Projections (tensor cores)
    gemm_bf16x3<<<ggrid, 256, 2 * STAGE>>>(pTEh, pTEl, pWh + 0 * 65536, pWl + 0 * 65536,
                                           bq, nullptr, pQ, N);
    gemm_bf16x3<<<ggrid, 256, 2 * STAGE>>>(pTEh, pTEl, pWh + 1 * 65536, pWl + 1 * 65536,
                                           bk, rel, pK, N);
    gemm_bf16x3<<<ggrid, 256, 2 * STAGE>>>(pXh, pXl, pWh + 2 * 65536, pWl + 2 * 65536,
                                           bv, nullptr, pV, N);

    // Attention: warp per destination column; emits bf16 hi/lo directly
    long long tthreads = (long long)N * 32;
    attn_kernel<<<(int)((tthreads + 255) / 256), 256>>>(N);

    // Output projection
    gemm_bf16x3<<<ggrid, 256, 2 * STAGE>>>(pNh, pNl, pWh + 3 * 65536, pWl + 3 * 65536,
                                           bo, nullptr, (float*)d_out, N);
}

// round 6
// speedup vs baseline: 2.3012x; 1.2113x over previous
#include <cuda_runtime.h>
#include <cuda_bf16.h>
#include <cuda_fp16.h>
#include <cstdint>
#include <cstddef>

#define IN_DIM   256
#define OUT_DIM  256
#define NHEAD    8
#define MAXN     50000
#define MAXE     800000

// ---------------- scratch (device globals; no allocation allowed) ----------
__device__ float  g_Q  [MAXN * OUT_DIM];
__device__ __half g_K16[MAXN * OUT_DIM];
__device__ __half g_V16[MAXN * OUT_DIM];

__device__ int   g_counts [MAXN + 4];
__device__ int   g_offsets[MAXN + 4];
__device__ int   g_csr    [MAXE];

__device__ __nv_bfloat16 g_TEhi[MAXN * IN_DIM];
__device__ __nv_bfloat16 g_TElo[MAXN * IN_DIM];
__device__ __nv_bfloat16 g_Xhi [MAXN * IN_DIM];
__device__ __nv_bfloat16 g_Xlo [MAXN * IN_DIM];
__device__ __nv_bfloat16 g_Nhi [MAXN * OUT_DIM];
__device__ __nv_bfloat16 g_Nlo [MAXN * OUT_DIM];
__device__ __nv_bfloat16 g_Whi [4 * 256 * 256];
__device__ __nv_bfloat16 g_Wlo [4 * 256 * 256];

// ---------------------------------------------------------------------------
__global__ void zero_kernel(float4* __restrict__ p, int n4) {
    int i = blockIdx.x * blockDim.x + threadIdx.x;
    if (i < n4) p[i] = make_float4(0.f, 0.f, 0.f, 0.f);
}

// ---------------------------------------------------------------------------
// fp32 -> (bf16 hi, bf16 lo) split, with optional concat of two sources.
struct alignas(8) bf4 { __nv_bfloat16 a, b, c, d; };

__device__ __forceinline__ void split_bf4(float4 v, bf4& h, bf4& l) {
    h.a = __float2bfloat16_rn(v.x); l.a = __float2bfloat16_rn(v.x - __bfloat162float(h.a));
    h.b = __float2bfloat16_rn(v.y); l.b = __float2bfloat16_rn(v.y - __bfloat162float(h.b));
    h.c = __float2bfloat16_rn(v.z); l.c = __float2bfloat16_rn(v.z - __bfloat162float(h.c));
    h.d = __float2bfloat16_rn(v.w); l.d = __float2bfloat16_rn(v.w - __bfloat162float(h.d));
}

__global__ void cvt_kernel(const float4* __restrict__ s0,
                           const float4* __restrict__ s1, int split4,
                           __nv_bfloat16* __restrict__ hi,
                           __nv_bfloat16* __restrict__ lo, int n4)
{
    int i = blockIdx.x * blockDim.x + threadIdx.x;
    if (i >= n4) return;
    float4 v = (i < split4) ? s0[i] : s1[i - split4];
    bf4 h, l;
    split_bf4(v, h, l);
    ((bf4*)hi)[i] = h;
    ((bf4*)lo)[i] = l;
}

// All 4 weight matrices in one launch: i in [0, 4*16384)
__global__ void cvt_w_kernel(const float4* __restrict__ w0, const float4* __restrict__ w1,
                             const float4* __restrict__ w2, const float4* __restrict__ w3,
                             __nv_bfloat16* __restrict__ hi, __nv_bfloat16* __restrict__ lo)
{
    int i = blockIdx.x * blockDim.x + threadIdx.x;
    if (i >= 4 * 16384) return;
    int m = i >> 14, j = i & 16383;
    const float4* src = (m == 0) ? w0 : (m == 1) ? w1 : (m == 2) ? w2 : w3;
    float4 v = src[j];
    bf4 h, l;
    split_bf4(v, h, l);
    ((bf4*)hi)[i] = h;
    ((bf4*)lo)[i] = l;
}

// ---------------------------------------------------------------------------
// mma helpers
__device__ __forceinline__ void ldsm4(uint32_t* r, uint32_t addr) {
    asm volatile("ldmatrix.sync.aligned.m8n8.x4.shared.b16 {%0,%1,%2,%3}, [%4];"
                 : "=r"(r[0]), "=r"(r[1]), "=r"(r[2]), "=r"(r[3]) : "r"(addr));
}
__device__ __forceinline__ void mma16816(float* d, const uint32_t* a,
                                         uint32_t b0, uint32_t b1) {
    asm volatile("mma.sync.aligned.m16n8k16.row.col.f32.bf16.bf16.f32 "
                 "{%0,%1,%2,%3}, {%4,%5,%6,%7}, {%8,%9}, {%0,%1,%2,%3};"
                 : "+f"(d[0]), "+f"(d[1]), "+f"(d[2]), "+f"(d[3])
                 : "r"(a[0]), "r"(a[1]), "r"(a[2]), "r"(a[3]), "r"(b0), "r"(b1));
}
__device__ __forceinline__ void cp16(uint32_t dst, const void* src, bool valid) {
    int sz = valid ? 16 : 0;
    asm volatile("cp.async.cg.shared.global [%0], [%1], 16, %2;"
                 :: "r"(dst), "l"(src), "r"(sz));
}

#define PITCH 40                       // bf16 elems per smem row (conflict-free)
#define PLANE (128 * PITCH * 2)        // 10240 B per operand plane
#define STAGE (4 * PLANE)              // 40960 B  (Ahi, Alo, Bhi, Blo)

__device__ __forceinline__ void gemm_prefetch(
    uint32_t d,
    const __nv_bfloat16* pah, const __nv_bfloat16* pal,
    const __nv_bfloat16* pbh, const __nv_bfloat16* pbl, bool a_valid)
{
    cp16(d + 0u * PLANE,       pah,     a_valid);
    cp16(d + 0u * PLANE + 16u, pah + 8, a_valid);
    cp16(d + 1u * PLANE,       pal,     a_valid);
    cp16(d + 1u * PLANE + 16u, pal + 8, a_valid);
    cp16(d + 2u * PLANE,       pbh,     true);
    cp16(d + 2u * PLANE + 16u, pbh + 8, true);
    cp16(d + 3u * PLANE,       pbl,     true);
    cp16(d + 3u * PLANE + 16u, pbl + 8, true);
    asm volatile("cp.async.commit_group;");
}

__device__ __forceinline__ void gemm_compute(
    uint32_t sb, uint32_t aoff, uint32_t boff, float acc[2][8][4])
{
#pragma unroll
    for (int kb = 0; kb < 2; kb++) {
        uint32_t ah[2][4], al[2][4];
#pragma unroll
        for (int ms = 0; ms < 2; ms++) {
            ldsm4(ah[ms], sb + 0u * PLANE + aoff + (uint32_t)(ms * 16 * PITCH * 2 + kb * 32));
            ldsm4(al[ms], sb + 1u * PLANE + aoff + (uint32_t)(ms * 16 * PITCH * 2 + kb * 32));
        }
#pragma unroll
        for (int np = 0; np < 4; np++) {
            uint32_t bh[4], bl[4];
            ldsm4(bh, sb + 2u * PLANE + boff + (uint32_t)(np * 16 * PITCH * 2 + kb * 32));
            ldsm4(bl, sb + 3u * PLANE + boff + (uint32_t)(np * 16 * PITCH * 2 + kb * 32));
#pragma unroll
            for (int ms = 0; ms < 2; ms++) {
                mma16816(acc[ms][np * 2 + 0], ah[ms], bh[0], bh[1]); // hi*hi
                mma16816(acc[ms][np * 2 + 1], ah[ms], bh[2], bh[3]);
                mma16816(acc[ms][np * 2 + 0], ah[ms], bl[0], bl[1]); // hi*lo
                mma16816(acc[ms][np * 2 + 1], ah[ms], bl[2], bl[3]);
                mma16816(acc[ms][np * 2 + 0], al[ms], bh[0], bh[1]); // lo*hi
                mma16816(acc[ms][np * 2 + 1], al[ms], bh[2], bh[3]);
            }
        }
    }
}

// C[M,256] = A[M,256] @ W[256,256]^T + bias (+rel), bf16x3 via mma.sync.
// OUTH=0: C is float*. OUTH=1: C is __half*.
template <int OUTH>
__global__ __launch_bounds__(256) void gemm_bf16x3(
    const __nv_bfloat16* __restrict__ Ahi, const __nv_bfloat16* __restrict__ Alo,
    const __nv_bfloat16* __restrict__ Whi, const __nv_bfloat16* __restrict__ Wlo,
    const float* __restrict__ bias, const float* __restrict__ rel,
    void* __restrict__ Cv, int M)
{
    extern __shared__ char smem[];
    uint32_t sbase = (uint32_t)__cvta_generic_to_shared(smem);

    const int tid = threadIdx.x, lane = tid & 31, wid = tid >> 5;
    const int warp_m = wid & 3, warp_n = wid >> 2;
    const int m0 = blockIdx.x * 128, n0 = blockIdx.y * 128;

    const int lrow = tid >> 1;
    const int lcs  = (tid & 1) * 16;
    const bool a_valid = (m0 + lrow) < M;
    const size_t a_row = (size_t)((m0 + lrow) < M ? (m0 + lrow) : (M - 1)) * 256;
    const size_t b_row = (size_t)(n0 + lrow) * 256;
    const uint32_t doff = (uint32_t)(lrow * PITCH + lcs) * 2u;

    float acc[2][8][4];
#pragma unroll
    for (int i = 0; i < 2; i++)
#pragma unroll
        for (int j = 0; j < 8; j++)
#pragma unroll
            for (int k = 0; k < 4; k++) acc[i][j][k] = 0.f;

    const uint32_t aoff = (uint32_t)(((warp_m * 32 + (lane & 15)) * PITCH
                                      + (lane >> 4) * 8) * 2);
    const uint32_t boff = (uint32_t)(((warp_n * 64 + (lane >> 4) * 8 + (lane & 7)) * PITCH
                                      + ((lane >> 3) & 1) * 8) * 2);

    gemm_prefetch(sbase + 0u * STAGE + doff,
                  Ahi + a_row + 0 + lcs, Alo + a_row + 0 + lcs,
                  Whi + b_row + 0 + lcs, Wlo + b_row + 0 + lcs, a_valid);
    gemm_prefetch(sbase + 1u * STAGE + doff,
                  Ahi + a_row + 32 + lcs, Alo + a_row + 32 + lcs,
                  Whi + b_row + 32 + lcs, Wlo + b_row + 32 + lcs, a_valid);

#pragma unroll
    for (int c = 0; c < 8; c++) {
        if (c < 7) asm volatile("cp.async.wait_group 1;");
        else       asm volatile("cp.async.wait_group 0;");
        __syncthreads();
        gemm_compute(sbase + (uint32_t)(c & 1) * STAGE, aoff, boff, acc);
        __syncthreads();
        if (c + 2 < 8) {
            int k0 = (c + 2) * 32;
            gemm_prefetch(sbase + (uint32_t)(c & 1) * STAGE + doff,
                          Ahi + a_row + k0 + lcs, Alo + a_row + k0 + lcs,
                          Whi + b_row + k0 + lcs, Wlo + b_row + k0 + lcs, a_valid);
        }
    }

    const int crow  = warp_m * 32 + (lane >> 2);
    const int ccol0 = warp_n * 64 + (lane & 3) * 2;
#pragma unroll
    for (int ns = 0; ns < 8; ns++) {
        int col = n0 + ccol0 + ns * 8;
        float av0 = bias[col]     + (rel ? rel[col]     : 0.f);
        float av1 = bias[col + 1] + (rel ? rel[col + 1] : 0.f);
#pragma unroll
        for (int ms = 0; ms < 2; ms++) {
#pragma unroll
            for (int rr = 0; rr < 2; rr++) {
                int r = m0 + crow + ms * 16 + rr * 8;
                if (r < M) {
                    float o0 = acc[ms][ns][rr * 2 + 0] + av0;
                    float o1 = acc[ms][ns][rr * 2 + 1] + av1;
                    if (OUTH) {
                        *(__half2*)((__half*)Cv + (size_t)r * 256 + col) =
                            __floats2half2_rn(o0, o1);
                    } else {
                        *(float2*)((float*)Cv + (size_t)r * 256 + col) =
                            make_float2(o0, o1);
                    }
                }
            }
        }
    }
}

// ---------------------------------------------------------------------------
// CSR build: histogram -> scan -> fill
__global__ void hist_kernel(const int* __restrict__ col, int E) {
    int i = blockIdx.x * blockDim.x + threadIdx.x;
    if (i < E) atomicAdd(&g_counts[col[i]], 1);
}

// Single-block scan, shuffle-based (3 barriers per 1024-chunk).
__global__ void scan_kernel(int n) {
    __shared__ int swarp[32];
    __shared__ int carry;
    int tid = threadIdx.x, lane = tid & 31, wid = tid >> 5;
    if (tid == 0) { carry = 0; g_offsets[0] = 0; }
    __syncthreads();
    for (int base = 0; base < n; base += 1024) {
        int i = base + tid;
        int v = (i < n) ? g_counts[i] : 0;
#pragma unroll
        for (int off = 1; off < 32; off <<= 1) {
            int t = __shfl_up_sync(0xFFFFFFFFu, v, off);
            if (lane >= off) v += t;
        }
        if (lane == 31) swarp[wid] = v;
        __syncthreads();
        if (wid == 0) {
            int w = swarp[lane];
#pragma unroll
            for (int off = 1; off < 32; off <<= 1) {
                int t = __shfl_up_sync(0xFFFFFFFFu, w, off);
                if (lane >= off) w += t;
            }
            swarp[lane] = w;
        }
        __syncthreads();
        int add = carry + ((wid > 0) ? swarp[wid - 1] : 0);
        if (i < n) g_offsets[i + 1] = v + add;
        int total = swarp[31];
        __syncthreads();
        if (tid == 0) carry += total;
        // next iteration's first __syncthreads orders carry/swarp reuse
    }
}

// After fill, g_offsets[c] = end of segment c; segment c = [off[c-1], off[c]).
__global__ void fill_kernel(const int* __restrict__ row,
                            const int* __restrict__ col, int E) {
    int i = blockIdx.x * blockDim.x + threadIdx.x;
    if (i < E) {
        int pos = atomicAdd(&g_offsets[col[i]], 1);
        g_csr[pos] = row[i];
    }
}

// ---------------------------------------------------------------------------
// One warp per destination column c. Q[c] (fp32) register-resident; gather
// fp16 K/V rows; accumulate softmax num/den in fp32 registers; normalize;
// emit bf16 hi/lo planes directly for the Wo GEMM.
__global__ __launch_bounds__(256) void attn_kernel(int N)
{
    int c = (blockIdx.x * blockDim.x + threadIdx.x) >> 5;
    if (c >= N) return;
    int lane = threadIdx.x & 31;

    int start = (c > 0) ? __ldg(&g_offsets[c - 1]) : 0;
    int end   = __ldg(&g_offsets[c]);

    const float4* qp = (const float4*)(g_Q + (size_t)c * OUT_DIM);
    float4 q0 = qp[lane * 2], q1 = qp[lane * 2 + 1];

    float4 n0 = make_float4(0.f, 0.f, 0.f, 0.f);
    float4 n1 = make_float4(0.f, 0.f, 0.f, 0.f);
    float den = 0.f;

    for (int i = start; i < end; i++) {
        int r = __ldg(&g_csr[i]);

        uint4 kraw = *(const uint4*)(g_K16 + (size_t)r * OUT_DIM + lane * 8);
        const __half2* kh = (const __half2*)&kraw;
        float2 k0 = __half22float2(kh[0]), k1 = __half22float2(kh[1]);
        float2 k2 = __half22float2(kh[2]), k3 = __half22float2(kh[3]);
        float p = q0.x * k0.x + q0.y * k0.y + q0.z * k1.x + q0.w * k1.y
                + q1.x * k2.x + q1.y * k2.y + q1.z * k3.x + q1.w * k3.y;
        p += __shfl_xor_sync(0xFFFFFFFFu, p, 1);   // reduce over the head's
        p += __shfl_xor_sync(0xFFFFFFFFu, p, 2);   // 4-lane quad
        float e = __expf(p * 0.17677669529663687f);  // 1/sqrt(32)

        uint4 vraw = *(const uint4*)(g_V16 + (size_t)r * OUT_DIM + lane * 8);
        const __half2* vh = (const __half2*)&vraw;
        float2 v0 = __half22float2(vh[0]), v1 = __half22float2(vh[1]);
        float2 v2 = __half22float2(vh[2]), v3 = __half22float2(vh[3]);
        n0.x += e * v0.x; n0.y += e * v0.y; n0.z += e * v1.x; n0.w += e * v1.y;
        n1.x += e * v2.x; n1.y += e * v2.y; n1.z += e * v3.x; n1.w += e * v3.y;
        den += e;   // all 4 lanes of a head hold identical e -> identical den
    }

    float inv = (den > 0.f) ? 1.0f / den : 0.f;
    n0.x *= inv; n0.y *= inv; n0.z *= inv; n0.w *= inv;
    n1.x *= inv; n1.y *= inv; n1.z *= inv; n1.w *= inv;

    bf4 h0, l0, h1, l1;
    split_bf4(n0, h0, l0);
    split_bf4(n1, h1, l1);

    bf4* hp = (bf4*)(g_Nhi + (size_t)c * OUT_DIM);
    bf4* lp = (bf4*)(g_Nlo + (size_t)c * OUT_DIM);
    hp[lane * 2]     = h0;  hp[lane * 2 + 1] = h1;
    lp[lane * 2]     = l0;  lp[lane * 2 + 1] = l1;
}

// ---------------------------------------------------------------------------
extern "C" void kernel_launch(void* const* d_in, const int* in_sizes, int n_in,
                              void* d_out, int out_size)
{
    const float* x   = (const float*)d_in[0];
    const int*   row = (const int*)  d_in[1];
    const int*   col = (const int*)  d_in[2];
    const float* rel = (const float*)d_in[3];
    const float* ute = (const float*)d_in[4];
    const float* ite = (const float*)d_in[5];
    const float* Wq  = (const float*)d_in[6];
    const float* bq  = (const float*)d_in[7];
    const float* Wk  = (const float*)d_in[8];
    const float* bk  = (const float*)d_in[9];
    const float* Wv  = (const float*)d_in[10];
    const float* bv  = (const float*)d_in[11];
    const float* Wo  = (const float*)d_in[12];
    const float* bo  = (const float*)d_in[13];

    const int N     = in_sizes[0] / IN_DIM;
    const int E     = in_sizes[1];
    const int split = in_sizes[4] / IN_DIM;

    float *pQ;
    __half *pK16, *pV16;
    int *pCounts;
    __nv_bfloat16 *pTEh, *pTEl, *pXh, *pXl, *pNh, *pNl, *pWh, *pWl;
    cudaGetSymbolAddress((void**)&pQ,     g_Q);
    cudaGetSymbolAddress((void**)&pK16,   g_K16);
    cudaGetSymbolAddress((void**)&pV16,   g_V16);
    cudaGetSymbolAddress((void**)&pCounts,g_counts);
    cudaGetSymbolAddress((void**)&pTEh,   g_TEhi);
    cudaGetSymbolAddress((void**)&pTEl,   g_TElo);
    cudaGetSymbolAddress((void**)&pXh,    g_Xhi);
    cudaGetSymbolAddress((void**)&pXl,    g_Xlo);
    cudaGetSymbolAddress((void**)&pNh,    g_Nhi);
    cudaGetSymbolAddress((void**)&pNl,    g_Nlo);
    cudaGetSymbolAddress((void**)&pWh,    g_Whi);
    cudaGetSymbolAddress((void**)&pWl,    g_Wlo);

    cudaFuncSetAttribute(gemm_bf16x3<0>,
                         cudaFuncAttributeMaxDynamicSharedMemorySize, 2 * STAGE);
    cudaFuncSetAttribute(gemm_bf16x3<1>,
                         cudaFuncAttributeMaxDynamicSharedMemorySize, 2 * STAGE);

    const int n4 = N * IN_DIM / 4;

    // fp32 -> bf16 hi/lo conversions (A operands + all 4 weights)
    cvt_kernel<<<(n4 + 255) / 256, 256>>>((const float4*)ute, (const float4*)ite,
                                          split * (IN_DIM / 4), pTEh, pTEl, n4);
    cvt_kernel<<<(n4 + 255) / 256, 256>>>((const float4*)x, (const float4*)x,
                                          n4, pXh, pXl, n4);
    cvt_w_kernel<<<(4 * 16384 + 255) / 256, 256>>>(
        (const float4*)Wq, (const float4*)Wk, (const float4*)Wv, (const float4*)Wo,
        pWh, pWl);

    // CSR build
    int c4 = (N + 3) / 4;
    zero_kernel<<<(c4 + 255) / 256, 256>>>((float4*)pCounts, c4);
    hist_kernel<<<(E + 255) / 256, 256>>>(col, E);
    scan_kernel<<<1, 1024>>>(N);
    fill_kernel<<<(E + 255) / 256, 256>>>(row, col, E);

    dim3 ggrid((N + 127) / 128, 2);

    // Projections: Q fp32, K+rel and V straight to fp16
    gemm_bf16x3<0><<<ggrid, 256, 2 * STAGE>>>(pTEh, pTEl, pWh + 0 * 65536, pWl + 0 * 65536,
                                              bq, nullptr, pQ, N);
    gemm_bf16x3<1><<<ggrid, 256, 2 * STAGE>>>(pTEh, pTEl, pWh + 1 * 65536, pWl + 1 * 65536,
                                              bk, rel, pK16, N);
    gemm_bf16x3<1><<<ggrid, 256, 2 * STAGE>>>(pXh, pXl, pWh + 2 * 65536, pWl + 2 * 65536,
                                              bv, nullptr, pV16, N);

    // Attention: warp per destination column; emits bf16 hi/lo directly
    long long tthreads = (long long)N * 32;
    attn_kernel<<<(int)((tthreads + 255) / 256), 256>>>(N);

    // Output projection
    gemm_bf16x3<0><<<ggrid, 256, 2 * STAGE>>>(pNh, pNl, pWh + 3 * 65536, pWl + 3 * 65536,
                                              bo, nullptr, (float*)d_out, N);
}

// round 10
// speedup vs baseline: 2.3189x; 1.0077x over previous
#include <cuda_runtime.h>
#include <cuda_bf16.h>
#include <cuda_fp16.h>
#include <cstdint>
#include <cstddef>

#define IN_DIM   256
#define OUT_DIM  256
#define NHEAD    8
#define MAXN     50000
#define MAXE     800000

// ---------------- scratch (device globals; no allocation allowed) ----------
__device__ float  g_Q  [MAXN * OUT_DIM];
__device__ __half g_K16[MAXN * OUT_DIM];
__device__ __half g_V16[MAXN * OUT_DIM];

__device__ int   g_counts [MAXN + 4];
__device__ int   g_offsets[MAXN + 4];
__device__ int   g_csr    [MAXE];

__device__ __nv_bfloat16 g_TEhi[MAXN * IN_DIM];
__device__ __nv_bfloat16 g_TElo[MAXN * IN_DIM];
__device__ __nv_bfloat16 g_Xhi [MAXN * IN_DIM];
__device__ __nv_bfloat16 g_Xlo [MAXN * IN_DIM];
__device__ __nv_bfloat16 g_Nhi [MAXN * OUT_DIM];
__device__ __nv_bfloat16 g_Nlo [MAXN * OUT_DIM];
__device__ __nv_bfloat16 g_Whi [4 * 256 * 256];
__device__ __nv_bfloat16 g_Wlo [4 * 256 * 256];

// ---------------------------------------------------------------------------
__global__ void zero_kernel(float4* __restrict__ p, int n4) {
    int i = blockIdx.x * blockDim.x + threadIdx.x;
    if (i < n4) p[i] = make_float4(0.f, 0.f, 0.f, 0.f);
}

// ---------------------------------------------------------------------------
struct alignas(8) bf4 { __nv_bfloat16 a, b, c, d; };

__device__ __forceinline__ void split_bf4(float4 v, bf4& h, bf4& l) {
    h.a = __float2bfloat16_rn(v.x); l.a = __float2bfloat16_rn(v.x - __bfloat162float(h.a));
    h.b = __float2bfloat16_rn(v.y); l.b = __float2bfloat16_rn(v.y - __bfloat162float(h.b));
    h.c = __float2bfloat16_rn(v.z); l.c = __float2bfloat16_rn(v.z - __bfloat162float(h.c));
    h.d = __float2bfloat16_rn(v.w); l.d = __float2bfloat16_rn(v.w - __bfloat162float(h.d));
}

__global__ void cvt_kernel(const float4* __restrict__ s0,
                           const float4* __restrict__ s1, int split4,
                           __nv_bfloat16* __restrict__ hi,
                           __nv_bfloat16* __restrict__ lo, int n4)
{
    int i = blockIdx.x * blockDim.x + threadIdx.x;
    if (i >= n4) return;
    float4 v = (i < split4) ? s0[i] : s1[i - split4];
    bf4 h, l;
    split_bf4(v, h, l);
    ((bf4*)hi)[i] = h;
    ((bf4*)lo)[i] = l;
}

__global__ void cvt_w_kernel(const float4* __restrict__ w0, const float4* __restrict__ w1,
                             const float4* __restrict__ w2, const float4* __restrict__ w3,
                             __nv_bfloat16* __restrict__ hi, __nv_bfloat16* __restrict__ lo)
{
    int i = blockIdx.x * blockDim.x + threadIdx.x;
    if (i >= 4 * 16384) return;
    int m = i >> 14, j = i & 16383;
    const float4* src = (m == 0) ? w0 : (m == 1) ? w1 : (m == 2) ? w2 : w3;
    float4 v = src[j];
    bf4 h, l;
    split_bf4(v, h, l);
    ((bf4*)hi)[i] = h;
    ((bf4*)lo)[i] = l;
}

// ---------------------------------------------------------------------------
// mma helpers
__device__ __forceinline__ void ldsm4(uint32_t* r, uint32_t addr) {
    asm volatile("ldmatrix.sync.aligned.m8n8.x4.shared.b16 {%0,%1,%2,%3}, [%4];"
                 : "=r"(r[0]), "=r"(r[1]), "=r"(r[2]), "=r"(r[3]) : "r"(addr));
}
__device__ __forceinline__ void mma16816(float* d, const uint32_t* a,
                                         uint32_t b0, uint32_t b1) {
    asm volatile("mma.sync.aligned.m16n8k16.row.col.f32.bf16.bf16.f32 "
                 "{%0,%1,%2,%3}, {%4,%5,%6,%7}, {%8,%9}, {%0,%1,%2,%3};"
                 : "+f"(d[0]), "+f"(d[1]), "+f"(d[2]), "+f"(d[3])
                 : "r"(a[0]), "r"(a[1]), "r"(a[2]), "r"(a[3]), "r"(b0), "r"(b1));
}
__device__ __forceinline__ void cp16(uint32_t dst, const void* src, bool valid) {
    int sz = valid ? 16 : 0;
    asm volatile("cp.async.cg.shared.global [%0], [%1], 16, %2;"
                 :: "r"(dst), "l"(src), "r"(sz));
}

#define PITCH 40                       // bf16 elems per smem row (conflict-free)
#define PLANE (128 * PITCH * 2)        // 10240 B per operand plane
#define STAGE (4 * PLANE)              // 40960 B  (Ahi, Alo, Bhi, Blo)

__device__ __forceinline__ void gemm_prefetch(
    uint32_t d,
    const __nv_bfloat16* pah, const __nv_bfloat16* pal,
    const __nv_bfloat16* pbh, const __nv_bfloat16* pbl, bool a_valid)
{
    cp16(d + 0u * PLANE,       pah,     a_valid);
    cp16(d + 0u * PLANE + 16u, pah + 8, a_valid);
    cp16(d + 1u * PLANE,       pal,     a_valid);
    cp16(d + 1u * PLANE + 16u, pal + 8, a_valid);
    cp16(d + 2u * PLANE,       pbh,     true);
    cp16(d + 2u * PLANE + 16u, pbh + 8, true);
    cp16(d + 3u * PLANE,       pbl,     true);
    cp16(d + 3u * PLANE + 16u, pbl + 8, true);
    asm volatile("cp.async.commit_group;");
}

__device__ __forceinline__ void gemm_compute(
    uint32_t sb, uint32_t aoff, uint32_t boff, float acc[2][8][4])
{
#pragma unroll
    for (int kb = 0; kb < 2; kb++) {
        uint32_t ah[2][4], al[2][4];
#pragma unroll
        for (int ms = 0; ms < 2; ms++) {
            ldsm4(ah[ms], sb + 0u * PLANE + aoff + (uint32_t)(ms * 16 * PITCH * 2 + kb * 32));
            ldsm4(al[ms], sb + 1u * PLANE + aoff + (uint32_t)(ms * 16 * PITCH * 2 + kb * 32));
        }
#pragma unroll
        for (int np = 0; np < 4; np++) {
            uint32_t bh[4], bl[4];
            ldsm4(bh, sb + 2u * PLANE + boff + (uint32_t)(np * 16 * PITCH * 2 + kb * 32));
            ldsm4(bl, sb + 3u * PLANE + boff + (uint32_t)(np * 16 * PITCH * 2 + kb * 32));
#pragma unroll
            for (int ms = 0; ms < 2; ms++) {
                mma16816(acc[ms][np * 2 + 0], ah[ms], bh[0], bh[1]); // hi*hi
                mma16816(acc[ms][np * 2 + 1], ah[ms], bh[2], bh[3]);
                mma16816(acc[ms][np * 2 + 0], ah[ms], bl[0], bl[1]); // hi*lo
                mma16816(acc[ms][np * 2 + 1], ah[ms], bl[2], bl[3]);
                mma16816(acc[ms][np * 2 + 0], al[ms], bh[0], bh[1]); // lo*hi
                mma16816(acc[ms][np * 2 + 1], al[ms], bh[2], bh[3]);
            }
        }
    }
}

// C[M,256] = A[M,256] @ W[256,256]^T + bias (+rel), bf16x3 via mma.sync.
// Block tile 128x128, 8 warps (4x2), K-chunks of 32, cp.async double buffer.
// min-blocks=2 clamps regs to 128 -> 2 CTAs/SM so sync bubbles overlap.
// OUTH=0: C is float*. OUTH=1: C is __half*.
template <int OUTH>
__global__ __launch_bounds__(256, 2) void gemm_bf16x3(
    const __nv_bfloat16* __restrict__ Ahi, const __nv_bfloat16* __restrict__ Alo,
    const __nv_bfloat16* __restrict__ Whi, const __nv_bfloat16* __restrict__ Wlo,
    const float* __restrict__ bias, const float* __restrict__ rel,
    void* __restrict__ Cv, int M)
{
    extern __shared__ char smem[];
    uint32_t sbase = (uint32_t)__cvta_generic_to_shared(smem);

    const int tid = threadIdx.x, lane = tid & 31, wid = tid >> 5;
    const int warp_m = wid & 3, warp_n = wid >> 2;
    const int m0 = blockIdx.x * 128, n0 = blockIdx.y * 128;

    const int lrow = tid >> 1;
    const int lcs  = (tid & 1) * 16;
    const bool a_valid = (m0 + lrow) < M;
    const size_t a_row = (size_t)((m0 + lrow) < M ? (m0 + lrow) : (M - 1)) * 256;
    const size_t b_row = (size_t)(n0 + lrow) * 256;
    const uint32_t doff = (uint32_t)(lrow * PITCH + lcs) * 2u;

    float acc[2][8][4];
#pragma unroll
    for (int i = 0; i < 2; i++)
#pragma unroll
        for (int j = 0; j < 8; j++)
#pragma unroll
            for (int k = 0; k < 4; k++) acc[i][j][k] = 0.f;

    const uint32_t aoff = (uint32_t)(((warp_m * 32 + (lane & 15)) * PITCH
                                      + (lane >> 4) * 8) * 2);
    const uint32_t boff = (uint32_t)(((warp_n * 64 + (lane >> 4) * 8 + (lane & 7)) * PITCH
                                      + ((lane >> 3) & 1) * 8) * 2);

    gemm_prefetch(sbase + 0u * STAGE + doff,
                  Ahi + a_row + 0 + lcs, Alo + a_row + 0 + lcs,
                  Whi + b_row + 0 + lcs, Wlo + b_row + 0 + lcs, a_valid);
    gemm_prefetch(sbase + 1u * STAGE + doff,
                  Ahi + a_row + 32 + lcs, Alo + a_row + 32 + lcs,
                  Whi + b_row + 32 + lcs, Wlo + b_row + 32 + lcs, a_valid);

#pragma unroll
    for (int c = 0; c < 8; c++) {
        if (c < 7) asm volatile("cp.async.wait_group 1;");
        else       asm volatile("cp.async.wait_group 0;");
        __syncthreads();
        gemm_compute(sbase + (uint32_t)(c & 1) * STAGE, aoff, boff, acc);
        __syncthreads();
        if (c + 2 < 8) {
            int k0 = (c + 2) * 32;
            gemm_prefetch(sbase + (uint32_t)(c & 1) * STAGE + doff,
                          Ahi + a_row + k0 + lcs, Alo + a_row + k0 + lcs,
                          Whi + b_row + k0 + lcs, Wlo + b_row + k0 + lcs, a_valid);
        }
    }

    const int crow  = warp_m * 32 + (lane >> 2);
    const int ccol0 = warp_n * 64 + (lane & 3) * 2;
#pragma unroll
    for (int ns = 0; ns < 8; ns++) {
        int col = n0 + ccol0 + ns * 8;
        float av0 = bias[col]     + (rel ? rel[col]     : 0.f);
        float av1 = bias[col + 1] + (rel ? rel[col + 1] : 0.f);
#pragma unroll
        for (int ms = 0; ms < 2; ms++) {
#pragma unroll
            for (int rr = 0; rr < 2; rr++) {
                int r = m0 + crow + ms * 16 + rr * 8;
                if (r < M) {
                    float o0 = acc[ms][ns][rr * 2 + 0] + av0;
                    float o1 = acc[ms][ns][rr * 2 + 1] + av1;
                    if (OUTH) {
                        *(__half2*)((__half*)Cv + (size_t)r * 256 + col) =
                            __floats2half2_rn(o0, o1);
                    } else {
                        *(float2*)((float*)Cv + (size_t)r * 256 + col) =
                            make_float2(o0, o1);
                    }
                }
            }
        }
    }
}

// ---------------------------------------------------------------------------
// CSR build: histogram -> scan -> fill
__global__ void hist_kernel(const int* __restrict__ col, int E) {
    int i = blockIdx.x * blockDim.x + threadIdx.x;
    if (i < E) atomicAdd(&g_counts[col[i]], 1);
}

// Single-block scan, shuffle-based (3 barriers per 1024-chunk).
__global__ void scan_kernel(int n) {
    __shared__ int swarp[32];
    __shared__ int carry;
    int tid = threadIdx.x, lane = tid & 31, wid = tid >> 5;
    if (tid == 0) { carry = 0; g_offsets[0] = 0; }
    __syncthreads();
    for (int base = 0; base < n; base += 1024) {
        int i = base + tid;
        int v = (i < n) ? g_counts[i] : 0;
#pragma unroll
        for (int off = 1; off < 32; off <<= 1) {
            int t = __shfl_up_sync(0xFFFFFFFFu, v, off);
            if (lane >= off) v += t;
        }
        if (lane == 31) swarp[wid] = v;
        __syncthreads();
        if (wid == 0) {
            int w = swarp[lane];
#pragma unroll
            for (int off = 1; off < 32; off <<= 1) {
                int t = __shfl_up_sync(0xFFFFFFFFu, w, off);
                if (lane >= off) w += t;
            }
            swarp[lane] = w;
        }
        __syncthreads();
        int add = carry + ((wid > 0) ? swarp[wid - 1] : 0);
        if (i < n) g_offsets[i + 1] = v + add;
        int total = swarp[31];
        __syncthreads();
        if (tid == 0) carry += total;
    }
}

// After fill, g_offsets[c] = end of segment c; segment c = [off[c-1], off[c]).
__global__ void fill_kernel(const int* __restrict__ row,
                            const int* __restrict__ col, int E) {
    int i = blockIdx.x * blockDim.x + threadIdx.x;
    if (i < E) {
        int pos = atomicAdd(&g_offsets[col[i]], 1);
        g_csr[pos] = row[i];
    }
}

// ---------------------------------------------------------------------------
// One warp per destination column c (fp16 K/V gathers, fp32 accumulate).
__global__ __launch_bounds__(256) void attn_kernel(int N)
{
    int c = (blockIdx.x * blockDim.x + threadIdx.x) >> 5;
    if (c >= N) return;
    int lane = threadIdx.x & 31;

    int start = (c > 0) ? __ldg(&g_offsets[c - 1]) : 0;
    int end   = __ldg(&g_offsets[c]);

    const float4* qp = (const float4*)(g_Q + (size_t)c * OUT_DIM);
    float4 q0 = qp[lane * 2], q1 = qp[lane * 2 + 1];

    float4 n0 = make_float4(0.f, 0.f, 0.f, 0.f);
    float4 n1 = make_float4(0.f, 0.f, 0.f, 0.f);
    float den = 0.f;

    for (int i = start; i < end; i++) {
        int r = __ldg(&g_csr[i]);

        uint4 kraw = *(const uint4*)(g_K16 + (size_t)r * OUT_DIM + lane * 8);
        const __half2* kh = (const __half2*)&kraw;
        float2 k0 = __half22float2(kh[0]), k1 = __half22float2(kh[1]);
        float2 k2 = __half22float2(kh[2]), k3 = __half22float2(kh[3]);
        float p = q0.x * k0.x + q0.y * k0.y + q0.z * k1.x + q0.w * k1.y
                + q1.x * k2.x + q1.y * k2.y + q1.z * k3.x + q1.w * k3.y;
        p += __shfl_xor_sync(0xFFFFFFFFu, p, 1);
        p += __shfl_xor_sync(0xFFFFFFFFu, p, 2);
        float e = __expf(p * 0.17677669529663687f);   // 1/sqrt(32)

        uint4 vraw = *(const uint4*)(g_V16 + (size_t)r * OUT_DIM + lane * 8);
        const __half2* vh = (const __half2*)&vraw;
        float2 v0 = __half22float2(vh[0]), v1 = __half22float2(vh[1]);
        float2 v2 = __half22float2(vh[2]), v3 = __half22float2(vh[3]);
        n0.x += e * v0.x; n0.y += e * v0.y; n0.z += e * v1.x; n0.w += e * v1.y;
        n1.x += e * v2.x; n1.y += e * v2.y; n1.z += e * v3.x; n1.w += e * v3.y;
        den += e;
    }

    float inv = (den > 0.f) ? 1.0f / den : 0.f;
    n0.x *= inv; n0.y *= inv; n0.z *= inv; n0.w *= inv;
    n1.x *= inv; n1.y *= inv; n1.z *= inv; n1.w *= inv;

    bf4 h0, l0, h1, l1;
    split_bf4(n0, h0, l0);
    split_bf4(n1, h1, l1);

    bf4* hp = (bf4*)(g_Nhi + (size_t)c * OUT_DIM);
    bf4* lp = (bf4*)(g_Nlo + (size_t)c * OUT_DIM);
    hp[lane * 2]     = h0;  hp[lane * 2 + 1] = h1;
    lp[lane * 2]     = l0;  lp[lane * 2 + 1] = l1;
}

// ---------------------------------------------------------------------------
extern "C" void kernel_launch(void* const* d_in, const int* in_sizes, int n_in,
                              void* d_out, int out_size)
{
    const float* x   = (const float*)d_in[0];
    const int*   row = (const int*)  d_in[1];
    const int*   col = (const int*)  d_in[2];
    const float* rel = (const float*)d_in[3];
    const float* ute = (const float*)d_in[4];
    const float* ite = (const float*)d_in[5];
    const float* Wq  = (const float*)d_in[6];
    const float* bq  = (const float*)d_in[7];
    const float* Wk  = (const float*)d_in[8];
    const float* bk  = (const float*)d_in[9];
    const float* Wv  = (const float*)d_in[10];
    const float* bv  = (const float*)d_in[11];
    const float* Wo  = (const float*)d_in[12];
    const float* bo  = (const float*)d_in[13];

    const int N     = in_sizes[0] / IN_DIM;
    const int E     = in_sizes[1];
    const int split = in_sizes[4] / IN_DIM;

    float *pQ;
    __half *pK16, *pV16;
    int *pCounts;
    __nv_bfloat16 *pTEh, *pTEl, *pXh, *pXl, *pNh, *pNl, *pWh, *pWl;
    cudaGetSymbolAddress((void**)&pQ,     g_Q);
    cudaGetSymbolAddress((void**)&pK16,   g_K16);
    cudaGetSymbolAddress((void**)&pV16,   g_V16);
    cudaGetSymbolAddress((void**)&pCounts,g_counts);
    cudaGetSymbolAddress((void**)&pTEh,   g_TEhi);
    cudaGetSymbolAddress((void**)&pTEl,   g_TElo);
    cudaGetSymbolAddress((void**)&pXh,    g_Xhi);
    cudaGetSymbolAddress((void**)&pXl,    g_Xlo);
    cudaGetSymbolAddress((void**)&pNh,    g_Nhi);
    cudaGetSymbolAddress((void**)&pNl,    g_Nlo);
    cudaGetSymbolAddress((void**)&pWh,    g_Whi);
    cudaGetSymbolAddress((void**)&pWl,    g_Wlo);

    cudaFuncSetAttribute(gemm_bf16x3<0>,
                         cudaFuncAttributeMaxDynamicSharedMemorySize, 2 * STAGE);
    cudaFuncSetAttribute(gemm_bf16x3<1>,
                         cudaFuncAttributeMaxDynamicSharedMemorySize, 2 * STAGE);

    const int n4 = N * IN_DIM / 4;

    // fp32 -> bf16 hi/lo conversions (A operands + all 4 weights)
    cvt_kernel<<<(n4 + 255) / 256, 256>>>((const float4*)ute, (const float4*)ite,
                                          split * (IN_DIM / 4), pTEh, pTEl, n4);
    cvt_kernel<<<(n4 + 255) / 256, 256>>>((const float4*)x, (const float4*)x,
                                          n4, pXh, pXl, n4);
    cvt_w_kernel<<<(4 * 16384 + 255) / 256, 256>>>(
        (const float4*)Wq, (const float4*)Wk, (const float4*)Wv, (const float4*)Wo,
        pWh, pWl);

    // CSR build
    int c4 = (N + 3) / 4;
    zero_kernel<<<(c4 + 255) / 256, 256>>>((float4*)pCounts, c4);
    hist_kernel<<<(E + 255) / 256, 256>>>(col, E);
    scan_kernel<<<1, 1024>>>(N);
    fill_kernel<<<(E + 255) / 256, 256>>>(row, col, E);

    dim3 ggrid((N + 127) / 128, 2);

    // Projections: Q fp32, K+rel and V straight to fp16
    gemm_bf16x3<0><<<ggrid, 256, 2 * STAGE>>>(pTEh, pTEl, pWh + 0 * 65536, pWl + 0 * 65536,
                                              bq, nullptr, pQ, N);
    gemm_bf16x3<1><<<ggrid, 256, 2 * STAGE>>>(pTEh, pTEl, pWh + 1 * 65536, pWl + 1 * 65536,
                                              bk, rel, pK16, N);
    gemm_bf16x3<1><<<ggrid, 256, 2 * STAGE>>>(pXh, pXl, pWh + 2 * 65536, pWl + 2 * 65536,
                                              bv, nullptr, pV16, N);

    // Attention: warp per destination column; emits bf16 hi/lo directly
    long long tthreads = (long long)N * 32;
    attn_kernel<<<(int)((tthreads + 255) / 256), 256>>>(N);

    // Output projection
    gemm_bf16x3<0><<<ggrid, 256, 2 * STAGE>>>(pNh, pNl, pWh + 3 * 65536, pWl + 3 * 65536,
                                              bo, nullptr, (float*)d_out, N);
}